// round 14
// baseline (speedup 1.0000x reference)
#include <cuda_runtime.h>
#include <cuda_fp16.h>
#include <cstdint>

#define Bx 8
#define Dx 128
#define Tx 4096
#define Kx 1024
#define Sx 8
#define ROWS (Bx*Tx)            // 32768
#define NCTAS (ROWS/128)        // 256
#define TAU 0.60f               // rescore window (4-sigma err + 2x key quant)
#define KEYMASK 0xFFFFFC00u
#define C2BIAS 512.0f           // makes folded distances strictly positive

// ---------------- device scratch (no runtime allocation) -------------------
__device__ float g_c2[Sx * Kx];                 // ||c||^2 fp32
__device__ float g_part[Sx * NCTAS];            // commit partials
// fp16 B fragment bundles: per (s,nt) tile: 128 rows x 256B (validated layout)
__device__ uint4 g_cbB[(size_t)Sx * Kx * 16];   // 2 MB

// ---------------- SMEM layout (byte offsets) --------------------------------
#define BROW    288           // padded B row stride (conflict-free LDS.64)
#define BBUF_H  18432         // 64 rows * 288  (half-tile buffer)
#define SMB_B   0             // 2 x BBUF_H = 36864
#define SMB_R   36864         // 128 x 132 fp32 = 67584
#define SMB_C2  104448        // 1024 fp32 = 4096  (BIASED by C2BIAS)
#define SMB_K1  108544        // 2 x 128 u32 (per N-half best key)
#define SMB_K2  109568        // 2 x 128 u32
#define SMB_K3  110592        // 2 x 128 u32
#define SMB_D2  111616        // 128 fp32 (half-1 rescore distance)
#define SMB_I2  112128        // 128 int  (half-1 rescore index)
#define SMB_IDX 112640        // 128 int
#define SMB_RED 113152        // 8 fp32 (per-warp commit partials)
#define SMEM_TOTAL 113184     // x2 = 226368 <= 228KB/SM -> 2 CTAs/SM

// ---------------- helpers ----------------------------------------------------
__device__ __forceinline__ uint32_t pack_f16(float a, float b) {
    __half2 h = __floats2half2_rn(a, b);
    return *reinterpret_cast<uint32_t*>(&h);
}
__device__ __forceinline__ uint32_t smem_u32(const void* p) {
    uint32_t a;
    asm("{ .reg .u64 t; cvta.to.shared.u64 t, %1; cvt.u32.u64 %0, t; }" : "=r"(a) : "l"(p));
    return a;
}

// m16n8k16 row.col fp16 MMA, fp32 accumulate (in place)
__device__ __forceinline__ void mma_f16(float* c, const uint32_t* a,
                                        uint32_t b0, uint32_t b1) {
    asm volatile(
        "mma.sync.aligned.m16n8k16.row.col.f32.f16.f16.f32 "
        "{%0,%1,%2,%3}, {%4,%5,%6,%7}, {%8,%9}, {%0,%1,%2,%3};"
        : "+f"(c[0]), "+f"(c[1]), "+f"(c[2]), "+f"(c[3])
        : "r"(a[0]), "r"(a[1]), "r"(a[2]), "r"(a[3]), "r"(b0), "r"(b1));
}

#define CP_ASYNC16(dst, src) \
    asm volatile("cp.async.cg.shared.global [%0], [%1], 16;" :: "r"(dst), "l"(src))
#define CP_COMMIT() asm volatile("cp.async.commit_group;" ::: "memory")
#define CP_WAIT0()  asm volatile("cp.async.wait_group 0;" ::: "memory")

// key for strictly-POSITIVE biased distances: raw float bits are order-
// preserving; low 10 mantissa bits carry the candidate index.
__device__ __forceinline__ uint32_t mk_key(float d, int n) {
    return (__float_as_uint(d) & KEYMASK) | (uint32_t)n;
}
__device__ __forceinline__ float key_to_f(uint32_t k) {
    return __uint_as_float(k & KEYMASK);   // biased value; bias cancels in gaps
}
// branchless sorted top-3 insert (ascending keys)
__device__ __forceinline__ void ins3(uint32_t& v1, uint32_t& v2, uint32_t& v3,
                                     uint32_t k) {
    uint32_t c  = v3 < k ? v3 : k;        // drop max(v3, k)
    uint32_t lo = v2 < c ? v2 : c;
    uint32_t hi = v2 < c ? c : v2;
    v3 = hi;
    uint32_t n1 = v1 < lo ? v1 : lo;
    v2 = v1 < lo ? lo : v1;
    v1 = n1;
}

// exact biased fp32 distance of SMEM residual row to codeword k (4-way ILP)
__device__ __forceinline__ float exact_dist(const float* R_row, const float* cbk,
                                            float c2biased) {
    const float4* rr4 = (const float4*)R_row;
    const float4* cp4 = (const float4*)cbk;
    float s0 = 0.f, s1 = 0.f, s2 = 0.f, s3 = 0.f;
    #pragma unroll
    for (int q = 0; q < 32; q += 4) {
        float4 a0 = rr4[q],     u0 = cp4[q];
        float4 a1 = rr4[q + 1], u1 = cp4[q + 1];
        float4 a2 = rr4[q + 2], u2 = cp4[q + 2];
        float4 a3 = rr4[q + 3], u3 = cp4[q + 3];
        s0 = fmaf(a0.x, u0.x, s0); s1 = fmaf(a0.y, u0.y, s1);
        s2 = fmaf(a0.z, u0.z, s2); s3 = fmaf(a0.w, u0.w, s3);
        s0 = fmaf(a1.x, u1.x, s0); s1 = fmaf(a1.y, u1.y, s1);
        s2 = fmaf(a1.z, u1.z, s2); s3 = fmaf(a1.w, u1.w, s3);
        s0 = fmaf(a2.x, u2.x, s0); s1 = fmaf(a2.y, u2.y, s1);
        s2 = fmaf(a2.z, u2.z, s2); s3 = fmaf(a2.w, u2.w, s3);
        s0 = fmaf(a3.x, u3.x, s0); s1 = fmaf(a3.y, u3.y, s1);
        s2 = fmaf(a3.z, u3.z, s2); s3 = fmaf(a3.w, u3.w, s3);
    }
    return fmaf(-2.0f, (s0 + s1) + (s2 + s3), c2biased);
}

// ---------------------------------------------------------------------------
// ||c||^2 for all stages: one warp per codeword.
// ---------------------------------------------------------------------------
__global__ void c2_kernel(const float* __restrict__ cb) {
    int w    = (blockIdx.x * blockDim.x + threadIdx.x) >> 5;
    int lane = threadIdx.x & 31;
    if (w >= Sx * Kx) return;
    float4 v = reinterpret_cast<const float4*>(cb)[(size_t)w * 32 + lane];
    float p = v.x * v.x + v.y * v.y + v.z * v.z + v.w * v.w;
    #pragma unroll
    for (int o = 16; o; o >>= 1) p += __shfl_down_sync(0xFFFFFFFFu, p, o);
    if (lane == 0) g_c2[w] = p;
}

// ---------------------------------------------------------------------------
// Codebooks -> fp16 fragment chunks (layout validated rounds 8-13).
// ---------------------------------------------------------------------------
__global__ void cvt_cb_kernel(const float* __restrict__ cb) {
    int idx = blockIdx.x * 256 + threadIdx.x;
    if (idx >= Sx * Kx * 16) return;
    int tp = idx & 1;
    int kc = (idx >> 1) & 7;
    int gk = idx >> 4;                           // s*Kx + n
    const float* row = cb + (size_t)gk * Dx + kc * 16 + 4 * tp;
    uint4 v;
    v.x = pack_f16(row[0], row[1]);
    v.y = pack_f16(row[8], row[9]);
    v.z = pack_f16(row[2], row[3]);
    v.w = pack_f16(row[10], row[11]);
    int s = gk >> 10, n = gk & 1023;
    size_t dst = ((size_t)(s * 8 + (n >> 7)) * 128 + (n & 127)) * 16 + kc * 2 + tp;
    g_cbB[dst] = v;
}

// ---------------------------------------------------------------------------
// Fused 8-stage RVQ: 1-pass fp16 mma, M=32/warp with N-split (B-fragment
// reuse x2), biased-key top-3 + parallel exact rescore.
// grid = 256 CTAs x 256 threads, 2 CTAs/SM.
// Warps 0-3: rows (wid&3)*32..+31, cols 0-31 of each half-tile.
// Warps 4-7: same rows, cols 32-63.
// ---------------------------------------------------------------------------
__global__ void __launch_bounds__(256, 2)
rvq_kernel(const float* __restrict__ x, const float* __restrict__ cb,
           float* __restrict__ out) {
    extern __shared__ char sm[];
    float*    R_sm = (float*)(sm + SMB_R);
    float*    c2s  = (float*)(sm + SMB_C2);
    uint32_t* k1s  = (uint32_t*)(sm + SMB_K1);   // [2][128]
    uint32_t* k2s  = (uint32_t*)(sm + SMB_K2);
    uint32_t* k3s  = (uint32_t*)(sm + SMB_K3);
    float*    d2s  = (float*)(sm + SMB_D2);
    int*      i2s  = (int*)(sm + SMB_I2);
    int*      sidx = (int*)(sm + SMB_IDX);
    float*    red  = (float*)(sm + SMB_RED);
    const uint32_t smb = smem_u32(sm);

    const int tid   = threadIdx.x;
    const int wid   = tid >> 5;
    const int lane  = tid & 31;
    const int g     = lane >> 2;
    const int tig   = lane & 3;
    const int grp   = wid >> 2;          // N-half group (0 or 1)
    const int mbase = (wid & 3) * 32;    // warp's 32-row base
    const int row0  = blockIdx.x * 128;
    const int b     = row0 >> 12;
    const int t0    = row0 & (Tx - 1);
    const size_t QOFF = (size_t)Bx * Dx * Tx;

    // ---- initial residual: R[t][d] = x[b][d][t0+t] (coalesced over t) ----
    #pragma unroll
    for (int it = 0; it < 64; it++) {
        int idx = it * 256 + tid;
        int d = idx >> 7, tl = idx & 127;
        R_sm[tl * 132 + d] = x[((size_t)b * Dx + d) * Tx + t0 + tl];
    }
    __syncthreads();

    #pragma unroll 1
    for (int s = 0; s < Sx; s++) {
        // ---- prefetch B half-tile 0 of this stage ----
        {
            const char* src = (const char*)(g_cbB + (size_t)(s * 8) * 2048);
            #pragma unroll
            for (int it = 0; it < 4; it++) {
                int idx = it * 256 + tid;
                int r = idx >> 4, c = idx & 15;
                CP_ASYNC16(smb + SMB_B + r * BROW + c * 16, src + r * 256 + c * 16);
            }
            CP_COMMIT();
        }

        // stage BIASED c2 into SMEM (guarantees positive folded distances)
        for (int i = tid; i < Kx; i += 256) c2s[i] = g_c2[s * Kx + i] + C2BIAS;

        // ---- A fragments (fp16): two m16 tiles (32 rows), reused all tiles ----
        uint32_t ah[2][8][4];
        #pragma unroll
        for (int t = 0; t < 2; t++) {
            #pragma unroll
            for (int kc = 0; kc < 8; kc++) {
                const float* base = &R_sm[(mbase + t * 16 + g) * 132
                                          + kc * 16 + 2 * tig];
                float2 p0 = *(const float2*)(base);
                float2 p1 = *(const float2*)(base + 8 * 132);
                float2 p2 = *(const float2*)(base + 8);
                float2 p3 = *(const float2*)(base + 8 * 132 + 8);
                ah[t][kc][0] = pack_f16(p0.x, p0.y);
                ah[t][kc][1] = pack_f16(p1.x, p1.y);
                ah[t][kc][2] = pack_f16(p2.x, p2.y);
                ah[t][kc][3] = pack_f16(p3.x, p3.y);
            }
        }

        // per-thread packed-key top-3 for four row-slots
        uint32_t K1[4], K2[4], K3[4];
        #pragma unroll
        for (int sl = 0; sl < 4; sl++) {
            K1[sl] = 0xFFFFFFFFu; K2[sl] = 0xFFFFFFFFu; K3[sl] = 0xFFFFFFFFu;
        }

        // ---- 16 half-tiles of 64 codewords, ping-pong buffered ----
        #pragma unroll 1
        for (int h = 0; h < 16; h++) {
            CP_WAIT0();
            __syncthreads();                 // half(h) visible; other buf free
            if (h < 15) {                    // prefetch h+1 into other buffer
                const char* src = (const char*)(g_cbB + (size_t)(s * 8) * 2048)
                                + (h + 1) * 16384;
                uint32_t dst = smb + SMB_B + ((h + 1) & 1) * BBUF_H;
                #pragma unroll
                for (int it = 0; it < 4; it++) {
                    int idx = it * 256 + tid;
                    int r = idx >> 4, c = idx & 15;
                    CP_ASYNC16(dst + r * BROW + c * 16, src + r * 256 + c * 16);
                }
                CP_COMMIT();
            }

            const char* bbase = sm + SMB_B + (h & 1) * BBUF_H;

            // 4 n-blocks for this warp's N-half; each B fragment feeds 2 MMAs
            #pragma unroll
            for (int nbg = 0; nbg < 4; nbg++) {
                int nb = grp * 4 + nbg;
                float a4[8] = {0.f, 0.f, 0.f, 0.f, 0.f, 0.f, 0.f, 0.f};
                #pragma unroll
                for (int kc = 0; kc < 8; kc++) {
                    uint2 bv = *(const uint2*)(bbase + (nb * 8 + g) * BROW
                                               + kc * 32 + tig * 8);
                    mma_f16(a4,     ah[0][kc], bv.x, bv.y);
                    mma_f16(a4 + 4, ah[1][kc], bv.x, bv.y);
                }
                int n0 = h * 64 + nb * 8 + 2 * tig;
                float2 cc = *(const float2*)&c2s[n0];
                // tile 0: slots 0 (row mbase+g) and 1 (row mbase+8+g)
                ins3(K1[0], K2[0], K3[0], mk_key(fmaf(-2.0f, a4[0], cc.x), n0));
                ins3(K1[0], K2[0], K3[0], mk_key(fmaf(-2.0f, a4[1], cc.y), n0 + 1));
                ins3(K1[1], K2[1], K3[1], mk_key(fmaf(-2.0f, a4[2], cc.x), n0));
                ins3(K1[1], K2[1], K3[1], mk_key(fmaf(-2.0f, a4[3], cc.y), n0 + 1));
                // tile 1: slots 2 (row mbase+16+g) and 3 (row mbase+24+g)
                ins3(K1[2], K2[2], K3[2], mk_key(fmaf(-2.0f, a4[4], cc.x), n0));
                ins3(K1[2], K2[2], K3[2], mk_key(fmaf(-2.0f, a4[5], cc.y), n0 + 1));
                ins3(K1[3], K2[3], K3[3], mk_key(fmaf(-2.0f, a4[6], cc.x), n0));
                ins3(K1[3], K2[3], K3[3], mk_key(fmaf(-2.0f, a4[7], cc.y), n0 + 1));
            }
        }

        // ---- merge top-3 across the 4 tig lanes, per slot ----
        #pragma unroll
        for (int sl = 0; sl < 4; sl++) {
            #pragma unroll
            for (int off = 1; off <= 2; off <<= 1) {
                uint32_t o1 = __shfl_xor_sync(0xFFFFFFFFu, K1[sl], off);
                uint32_t o2 = __shfl_xor_sync(0xFFFFFFFFu, K2[sl], off);
                uint32_t o3 = __shfl_xor_sync(0xFFFFFFFFu, K3[sl], off);
                ins3(K1[sl], K2[sl], K3[sl], o1);
                ins3(K1[sl], K2[sl], K3[sl], o2);
                ins3(K1[sl], K2[sl], K3[sl], o3);
            }
        }
        if (tig == 0) {
            #pragma unroll
            for (int sl = 0; sl < 4; sl++) {
                int row = mbase + (sl >> 1) * 16 + (sl & 1) * 8 + g;
                k1s[grp * 128 + row] = K1[sl];
                k2s[grp * 128 + row] = K2[sl];
                k3s[grp * 128 + row] = K3[sl];
            }
        }
        __syncthreads();

        // ---- pick: merge the two N-half top-3 sets, then parallel rescore ----
        {
            const int row  = tid & 127;
            const int half = tid >> 7;
            uint32_t k1 = k1s[row], k2 = k2s[row], k3 = k3s[row];
            ins3(k1, k2, k3, k1s[128 + row]);
            ins3(k1, k2, k3, k2s[128 + row]);
            ins3(k1, k2, k3, k3s[128 + row]);
            float f1 = key_to_f(k1);
            bool trig = (key_to_f(k2) - f1 < TAU);
            bool has3 = trig && (key_to_f(k3) - f1 < TAU);
            float bestd = __int_as_float(0x7F800000);
            int   besti = 0x7fffffff;
            if (trig) {
                int c0 = half ? (int)(k2 & 1023) : (int)(k1 & 1023);
                bestd = exact_dist(&R_sm[row * 132],
                                   cb + ((size_t)s * Kx + c0) * Dx, c2s[c0]);
                besti = c0;
                if (!half && has3) {
                    int c2i = (int)(k3 & 1023);
                    float dx = exact_dist(&R_sm[row * 132],
                                          cb + ((size_t)s * Kx + c2i) * Dx, c2s[c2i]);
                    if (dx < bestd || (dx == bestd && c2i < besti)) {
                        bestd = dx; besti = c2i;
                    }
                }
            }
            if (half) { d2s[row] = bestd; i2s[row] = besti; }
            __syncthreads();
            if (!half) {
                int bi = (int)(k1 & 1023);
                if (trig) {
                    float dB = d2s[row]; int iB = i2s[row];
                    if (dB < bestd || (dB == bestd && iB < besti)) {
                        bestd = dB; besti = iB;
                    }
                    bi = besti;
                }
                sidx[row] = bi;
                out[QOFF + (size_t)s * ROWS + row0 + row] = (float)bi;
            }
        }
        __syncthreads();

        // ---- residual update + commit partial (warp-shuffle reduction) ----
        float cm = 0.0f;
        #pragma unroll
        for (int it = 0; it < 64; it++) {
            int idx = it * 256 + tid;
            int m = idx >> 7, d = idx & 127;
            int k = sidx[m];
            float q  = cb[((size_t)s * Kx + k) * Dx + d];
            float r  = R_sm[m * 132 + d];
            float nr = r - q;
            cm = fmaf(nr, nr, cm);
            R_sm[m * 132 + d] = nr;
        }
        #pragma unroll
        for (int o = 16; o; o >>= 1) cm += __shfl_down_sync(0xFFFFFFFFu, cm, o);
        if (lane == 0) red[wid] = cm;
        __syncthreads();
        if (tid == 0) {
            float ssum = 0.0f;
            #pragma unroll
            for (int w = 0; w < 8; w++) ssum += red[w];
            g_part[s * NCTAS + blockIdx.x] = ssum;
        }
        __syncthreads();
    }

    // ---- quantized output: out[b][d][t] = x - R_final ----
    #pragma unroll
    for (int it = 0; it < 64; it++) {
        int idx = it * 256 + tid;
        int d = idx >> 7, tl = idx & 127;
        size_t go = ((size_t)b * Dx + d) * Tx + t0 + tl;
        out[go] = x[go] - R_sm[tl * 132 + d];
    }
}

// ---------------------------------------------------------------------------
// bw + penalty
// ---------------------------------------------------------------------------
__global__ void pack_kernel(float* __restrict__ out) {
    __shared__ float red[256];
    const size_t COFF = (size_t)Bx * Dx * Tx + (size_t)Sx * ROWS;
    int tid = threadIdx.x;
    float s = 0.0f;
    for (int i = tid; i < Sx * NCTAS; i += 256) s += g_part[i];
    red[tid] = s;
    __syncthreads();
    #pragma unroll
    for (int st = 128; st > 0; st >>= 1) {
        if (tid < st) red[tid] += red[tid + st];
        __syncthreads();
    }
    if (tid == 0) {
        out[COFF + 0] = 6000.0f;   // 8 * log2(1024) * 75
        out[COFF + 1] = red[0] / ((float)Sx * (float)ROWS * (float)Dx);
    }
}

extern "C" void kernel_launch(void* const* d_in, const int* in_sizes, int n_in,
                              void* d_out, int out_size) {
    const float* x  = (const float*)d_in[0];
    const float* cb = (const float*)d_in[1];
    float* out = (float*)d_out;

    cudaFuncSetAttribute(rvq_kernel, cudaFuncAttributeMaxDynamicSharedMemorySize,
                         SMEM_TOTAL);

    c2_kernel<<<(Sx * Kx * 32) / 256, 256>>>(cb);
    cvt_cb_kernel<<<(Sx * Kx * 16) / 256, 256>>>(cb);
    rvq_kernel<<<NCTAS, 256, SMEM_TOTAL>>>(x, cb, out);
    pack_kernel<<<1, 256>>>(out);
}